// round 5
// baseline (speedup 1.0000x reference)
#include <cuda_runtime.h>
#include <cstdint>
#include <math.h>

#define BATCH 16
#define HID   1024
#define G4    (4*HID)
#define TSTEPS 257
#define VOC   1024
#define EMB   512
#define SEQ   512
#define ENC2D 1024
#define SOS_TOK 1
#define EOS_TOK 2
#define NTHR 256

// ---------------- device scratch ----------------
__device__ float g_P0[VOC * G4];
__device__ float g_h[2][BATCH * HID];
__device__ float g_hs[TSTEPS * BATCH * HID];
__device__ float g_ctx[TSTEPS * BATCH * HID];
__device__ float g_partial[TSTEPS];
__device__ unsigned g_barcnt = 0;
__device__ unsigned g_bargen = 0;

__device__ __forceinline__ float4 ld4(const float* p) {
    return *reinterpret_cast<const float4*>(p);
}
__device__ __forceinline__ void grid_sync() {
    __syncthreads();
    if (threadIdx.x == 0) {
        volatile unsigned* vg = &g_bargen;
        unsigned gen = *vg;
        __threadfence();
        unsigned arr = atomicAdd(&g_barcnt, 1u);
        if (arr == gridDim.x - 1) {
            g_barcnt = 0u;
            __threadfence();
            atomicAdd(&g_bargen, 1u);
        } else {
            while (*vg == gen) { __nanosleep(64); }
        }
        __threadfence();
    }
    __syncthreads();
}
__device__ __forceinline__ void wreduce16(float a[16]) {
#pragma unroll
    for (int b = 0; b < 16; b++) {
#pragma unroll
        for (int off = 16; off; off >>= 1)
            a[b] += __shfl_xor_sync(0xffffffffu, a[b], off);
    }
}
__device__ __forceinline__ float pick16(const float a[16], int lane) {
    float r = 0.f;
#pragma unroll
    for (int b = 0; b < 16; b++) r = (lane == b) ? a[b] : r;
    return r;
}
__device__ __forceinline__ float sigmoidf_(float x) { return 1.f / (1.f + __expf(-x)); }

// Accumulate gate rows {jj, H+jj, 2H+jj, 3H+jj} of W against 16 vectors in smem.
__device__ __forceinline__ void accum_gates(const float* __restrict__ W, int jj,
                                            const float* __restrict__ sh, int lane,
                                            float a0[16], float a1[16],
                                            float a2[16], float a3[16]) {
    const float* Wi = W + (size_t)(0 * HID + jj) * HID;
    const float* Wf = W + (size_t)(1 * HID + jj) * HID;
    const float* Wg = W + (size_t)(2 * HID + jj) * HID;
    const float* Wo = W + (size_t)(3 * HID + jj) * HID;
#pragma unroll 2
    for (int i = 0; i < HID / 128; i++) {
        int k = 4 * lane + 128 * i;
        float4 wi = ld4(Wi + k), wf = ld4(Wf + k), wg = ld4(Wg + k), wo = ld4(Wo + k);
#pragma unroll
        for (int b = 0; b < 16; b++) {
            float4 h4 = ld4(sh + b * HID + k);
            a0[b] += wi.x * h4.x + wi.y * h4.y + wi.z * h4.z + wi.w * h4.w;
            a1[b] += wf.x * h4.x + wf.y * h4.y + wf.z * h4.z + wf.w * h4.w;
            a2[b] += wg.x * h4.x + wg.y * h4.y + wg.z * h4.z + wg.w * h4.w;
            a3[b] += wo.x * h4.x + wo.y * h4.y + wo.z * h4.z + wo.w * h4.w;
        }
    }
}

// ---------------- P0: emb@W_ih0[:, :512]^T + b_ih0 + b_hh0 ----------------
__global__ void __launch_bounds__(NTHR) p0_kernel(const float* __restrict__ emb,
                                                  const float* __restrict__ Wih0,
                                                  const float* __restrict__ bih0,
                                                  const float* __restrict__ bhh0) {
    __shared__ float se[16 * EMB];
    const int tid = threadIdx.x, lane = tid & 31, w = tid >> 5;
    const int v0 = blockIdx.x * 16;
    for (int i = tid; i < 16 * EMB; i += NTHR)
        se[i] = emb[(size_t)(v0 + (i >> 9)) * EMB + (i & 511)];
    __syncthreads();
    const int jbase = blockIdx.y * 1024;
    for (int j = jbase + w; j < jbase + 1024; j += 8) {
        float acc[16];
#pragma unroll
        for (int b = 0; b < 16; b++) acc[b] = 0.f;
#pragma unroll
        for (int i = 0; i < EMB / 128; i++) {
            int k = 4 * lane + 128 * i;
            float4 w4 = ld4(Wih0 + (size_t)j * (EMB + ENC2D) + k);
#pragma unroll
            for (int v = 0; v < 16; v++) {
                float4 e4 = ld4(se + v * EMB + k);
                acc[v] += w4.x * e4.x + w4.y * e4.y + w4.z * e4.z + w4.w * e4.w;
            }
        }
        wreduce16(acc);
        if (lane < 16)
            g_P0[(size_t)(v0 + lane) * G4 + j] = pick16(acc, lane) + bih0[j] + bhh0[j];
    }
}

// ---------------- persistent 3-layer LSTM ----------------
__global__ void __launch_bounds__(NTHR, 1) rec_kernel(
    const int* __restrict__ tokens,
    const float* __restrict__ Whh0,
    const float* __restrict__ Wih1, const float* __restrict__ Whh1,
    const float* __restrict__ Wih2, const float* __restrict__ Whh2,
    const float* __restrict__ bih1, const float* __restrict__ bhh1,
    const float* __restrict__ bih2, const float* __restrict__ bhh2) {
    extern __shared__ float sm[];
    float* H0 = sm;
    float* H1 = sm + BATCH * HID;
    float* H2 = sm + 2 * BATCH * HID;
    const int tid = threadIdx.x, lane = tid & 31, w = tid >> 5;
    const int jj = blockIdx.x * 8 + w;

    for (int i = tid; i < 3 * BATCH * HID; i += NTHR) sm[i] = 0.f;
    __syncthreads();
    float c0 = 0.f, c1 = 0.f, c2 = 0.f;

    for (int t = 0; t < TSTEPS; t++) {
        float a0[16], a1[16], a2[16], a3[16];
        // layer 0
#pragma unroll
        for (int b = 0; b < 16; b++) { a0[b] = 0.f; a1[b] = 0.f; a2[b] = 0.f; a3[b] = 0.f; }
        accum_gates(Whh0, jj, H0, lane, a0, a1, a2, a3);
        wreduce16(a0); wreduce16(a1); wreduce16(a2); wreduce16(a3);
        if (lane < BATCH) {
            int tok = (t == 0) ? SOS_TOK : tokens[lane * 256 + (t - 1)];
            const float* p = g_P0 + (size_t)tok * G4 + jj;
            float iv = sigmoidf_(pick16(a0, lane) + p[0]);
            float fv = sigmoidf_(pick16(a1, lane) + p[HID]);
            float gv = tanhf(pick16(a2, lane) + p[2 * HID]);
            float ov = sigmoidf_(pick16(a3, lane) + p[3 * HID]);
            c0 = fv * c0 + iv * gv;
            g_h[0][lane * HID + jj] = ov * tanhf(c0);
        }
        grid_sync();
        for (int i = tid; i < BATCH * HID; i += NTHR) H0[i] = __ldcg(&g_h[0][i]);
        __syncthreads();
        // layer 1
#pragma unroll
        for (int b = 0; b < 16; b++) { a0[b] = 0.f; a1[b] = 0.f; a2[b] = 0.f; a3[b] = 0.f; }
        accum_gates(Wih1, jj, H0, lane, a0, a1, a2, a3);
        accum_gates(Whh1, jj, H1, lane, a0, a1, a2, a3);
        wreduce16(a0); wreduce16(a1); wreduce16(a2); wreduce16(a3);
        if (lane < BATCH) {
            float iv = sigmoidf_(pick16(a0, lane) + bih1[jj] + bhh1[jj]);
            float fv = sigmoidf_(pick16(a1, lane) + bih1[HID + jj] + bhh1[HID + jj]);
            float gv = tanhf(pick16(a2, lane) + bih1[2 * HID + jj] + bhh1[2 * HID + jj]);
            float ov = sigmoidf_(pick16(a3, lane) + bih1[3 * HID + jj] + bhh1[3 * HID + jj]);
            c1 = fv * c1 + iv * gv;
            g_h[1][lane * HID + jj] = ov * tanhf(c1);
        }
        grid_sync();
        for (int i = tid; i < BATCH * HID; i += NTHR) H1[i] = __ldcg(&g_h[1][i]);
        __syncthreads();
        // layer 2
#pragma unroll
        for (int b = 0; b < 16; b++) { a0[b] = 0.f; a1[b] = 0.f; a2[b] = 0.f; a3[b] = 0.f; }
        accum_gates(Wih2, jj, H1, lane, a0, a1, a2, a3);
        accum_gates(Whh2, jj, H2, lane, a0, a1, a2, a3);
        wreduce16(a0); wreduce16(a1); wreduce16(a2); wreduce16(a3);
        if (lane < BATCH) {
            float iv = sigmoidf_(pick16(a0, lane) + bih2[jj] + bhh2[jj]);
            float fv = sigmoidf_(pick16(a1, lane) + bih2[HID + jj] + bhh2[HID + jj]);
            float gv = tanhf(pick16(a2, lane) + bih2[2 * HID + jj] + bhh2[2 * HID + jj]);
            float ov = sigmoidf_(pick16(a3, lane) + bih2[3 * HID + jj] + bhh2[3 * HID + jj]);
            c2 = fv * c2 + iv * gv;
            g_hs[(size_t)t * (BATCH * HID) + lane * HID + jj] = ov * tanhf(c2);
        }
        grid_sync();
        {
            const float* src = g_hs + (size_t)t * (BATCH * HID);
            for (int i = tid; i < BATCH * HID; i += NTHR) H2[i] = __ldcg(&src[i]);
        }
        __syncthreads();
    }
}

// ---------------- attention: 16 t-steps per block, one batch ----------------
__global__ void __launch_bounds__(NTHR, 1) attn_kernel(const float* __restrict__ enc) {
    extern __shared__ float sm[];
    float* sh_hs = sm;                 // [16][1024]
    float* sh_sc = sm + BATCH * HID;   // [512][16]
    const int tid = threadIdx.x, lane = tid & 31, w = tid >> 5;
    const int b = blockIdx.y, t0 = blockIdx.x * 16;

    for (int i = tid; i < 16 * HID; i += NTHR) {
        int t = t0 + (i >> 10);
        sh_hs[i] = (t < TSTEPS) ? g_hs[(size_t)t * (BATCH * HID) + b * HID + (i & 1023)] : 0.f;
    }
    __syncthreads();
    const float* encb = enc + (size_t)b * SEQ * ENC2D;

    for (int s = w; s < SEQ; s += 8) {
        float acc[16];
#pragma unroll
        for (int i = 0; i < 16; i++) acc[i] = 0.f;
#pragma unroll 2
        for (int i = 0; i < ENC2D / 128; i++) {
            int k = 4 * lane + 128 * i;
            float4 e4 = ld4(encb + (size_t)s * ENC2D + k);
#pragma unroll
            for (int tt = 0; tt < 16; tt++) {
                float4 h4 = ld4(sh_hs + tt * HID + k);
                acc[tt] += e4.x * h4.x + e4.y * h4.y + e4.z * h4.z + e4.w * h4.w;
            }
        }
        wreduce16(acc);
        if (lane < 16) sh_sc[s * 16 + lane] = pick16(acc, lane);
    }
    __syncthreads();

    // softmax over s for each tt; warp w handles tt = 2w, 2w+1
#pragma unroll
    for (int r = 0; r < 2; r++) {
        int tt = 2 * w + r;
        float v[16], mx = -1e30f;
#pragma unroll
        for (int i = 0; i < 16; i++) { v[i] = sh_sc[(lane + 32 * i) * 16 + tt]; mx = fmaxf(mx, v[i]); }
#pragma unroll
        for (int o = 16; o; o >>= 1) mx = fmaxf(mx, __shfl_xor_sync(0xffffffffu, mx, o));
        float sum = 0.f;
#pragma unroll
        for (int i = 0; i < 16; i++) { v[i] = __expf(v[i] - mx); sum += v[i]; }
#pragma unroll
        for (int o = 16; o; o >>= 1) sum += __shfl_xor_sync(0xffffffffu, sum, o);
        float inv = 1.f / sum;
#pragma unroll
        for (int i = 0; i < 16; i++) sh_sc[(lane + 32 * i) * 16 + tt] = v[i] * inv;
    }
    __syncthreads();

    // ctx[tt][k] = sum_s attn[tt][s] * enc[b][s][k]; thread owns 4 k's
    float acc[4][16];
#pragma unroll
    for (int q = 0; q < 4; q++)
#pragma unroll
        for (int tt = 0; tt < 16; tt++) acc[q][tt] = 0.f;
    for (int s = 0; s < SEQ; s++) {
        float4 a0 = ld4(sh_sc + s * 16);
        float4 a1 = ld4(sh_sc + s * 16 + 4);
        float4 a2 = ld4(sh_sc + s * 16 + 8);
        float4 a3 = ld4(sh_sc + s * 16 + 12);
        float at[16] = {a0.x,a0.y,a0.z,a0.w,a1.x,a1.y,a1.z,a1.w,
                        a2.x,a2.y,a2.z,a2.w,a3.x,a3.y,a3.z,a3.w};
#pragma unroll
        for (int q = 0; q < 4; q++) {
            float e = encb[(size_t)s * ENC2D + tid + 256 * q];
#pragma unroll
            for (int tt = 0; tt < 16; tt++) acc[q][tt] += at[tt] * e;
        }
    }
#pragma unroll
    for (int tt = 0; tt < 16; tt++) {
        int t = t0 + tt;
        if (t < TSTEPS) {
#pragma unroll
            for (int q = 0; q < 4; q++)
                g_ctx[(size_t)t * (BATCH * HID) + b * HID + tid + 256 * q] = acc[q][tt];
        }
    }
}

// ---------------- fused MLP + logits + NLL per t (16 rows) ----------------
__global__ void __launch_bounds__(NTHR, 1) mlp_kernel(
    const int* __restrict__ tokens,
    const float* __restrict__ W1, const float* __restrict__ b1,
    const float* __restrict__ W2, const float* __restrict__ b2) {
    extern __shared__ float sm[];
    float* sx = sm;                       // [16][2048]
    float* sh = sm + 16 * 2048;           // [16][1024]
    float* red = sm + 16 * 2048 + 16 * 1024;  // [8][16][3]
    const int tid = threadIdx.x, lane = tid & 31, w = tid >> 5;
    const int t = blockIdx.x;

    for (int i = tid; i < 16 * 1024; i += NTHR) {
        int b = i >> 10, k = i & 1023;
        sx[b * 2048 + k] = g_hs[(size_t)t * (BATCH * HID) + i];
        sx[b * 2048 + 1024 + k] = g_ctx[(size_t)t * (BATCH * HID) + i];
    }
    __syncthreads();

    for (int j = w; j < 1024; j += 8) {
        float acc[16];
#pragma unroll
        for (int b = 0; b < 16; b++) acc[b] = 0.f;
#pragma unroll 2
        for (int i = 0; i < 2048 / 128; i++) {
            int k = 4 * lane + 128 * i;
            float4 w4 = ld4(W1 + (size_t)j * 2048 + k);
#pragma unroll
            for (int b = 0; b < 16; b++) {
                float4 x4 = ld4(sx + b * 2048 + k);
                acc[b] += w4.x * x4.x + w4.y * x4.y + w4.z * x4.z + w4.w * x4.w;
            }
        }
        wreduce16(acc);
        if (lane < 16) sh[lane * 1024 + j] = tanhf(pick16(acc, lane) + b1[j]);
    }
    __syncthreads();

    // logits + streaming logsumexp + target pick
    float M[16], S[16], TV[16];
#pragma unroll
    for (int b = 0; b < 16; b++) { M[b] = -1e30f; S[b] = 0.f; TV[b] = 0.f; }
    int tgt[16];
#pragma unroll
    for (int b = 0; b < 16; b++) tgt[b] = (t < 256) ? tokens[b * 256 + t] : EOS_TOK;

    for (int j = w; j < 1024; j += 8) {
        float acc[16];
#pragma unroll
        for (int b = 0; b < 16; b++) acc[b] = 0.f;
#pragma unroll 2
        for (int i = 0; i < 1024 / 128; i++) {
            int k = 4 * lane + 128 * i;
            float4 w4 = ld4(W2 + (size_t)j * 1024 + k);
#pragma unroll
            for (int b = 0; b < 16; b++) {
                float4 h4 = ld4(sh + b * 1024 + k);
                acc[b] += w4.x * h4.x + w4.y * h4.y + w4.z * h4.z + w4.w * h4.w;
            }
        }
        wreduce16(acc);
        float bj = b2[j];
#pragma unroll
        for (int b = 0; b < 16; b++) {
            float val = acc[b] + bj;
            float mn = fmaxf(M[b], val);
            S[b] = S[b] * __expf(M[b] - mn) + __expf(val - mn);
            M[b] = mn;
            if (j == tgt[b]) TV[b] = val;
        }
    }
    if (lane == 0) {
#pragma unroll
        for (int b = 0; b < 16; b++) {
            red[(w * 16 + b) * 3 + 0] = M[b];
            red[(w * 16 + b) * 3 + 1] = S[b];
            red[(w * 16 + b) * 3 + 2] = TV[b];
        }
    }
    __syncthreads();
    if (w == 0 && lane < 16) {
        float m = -1e30f, s = 0.f, tv = 0.f;
        for (int ww = 0; ww < 8; ww++) {
            float mw = red[(ww * 16 + lane) * 3 + 0];
            float sw = red[(ww * 16 + lane) * 3 + 1];
            tv += red[(ww * 16 + lane) * 3 + 2];
            float mn = fmaxf(m, mw);
            s = s * __expf(m - mn) + sw * __expf(mw - mn);
            m = mn;
        }
        float nll = (m + logf(s)) - tv;
#pragma unroll
        for (int o = 8; o; o >>= 1) nll += __shfl_xor_sync(0xffffu, nll, o);
        if (lane == 0) g_partial[t] = nll;
    }
}

__global__ void reduce_kernel(float* out) {
    __shared__ float s[256];
    int tid = threadIdx.x;
    float v = g_partial[tid];
    if (tid == 0) v += g_partial[256];
    s[tid] = v; __syncthreads();
    for (int o = 128; o; o >>= 1) { if (tid < o) s[tid] += s[tid + o]; __syncthreads(); }
    if (tid == 0) out[0] = s[0] / (float)(TSTEPS * BATCH);
}

extern "C" void kernel_launch(void* const* d_in, const int* in_sizes, int n_in,
                              void* d_out, int out_size) {
    const int*   tokens = (const int*)d_in[0];
    const float* enc    = (const float*)d_in[1];
    const float* emb    = (const float*)d_in[2];
    const float* Wih0   = (const float*)d_in[3];
    const float* Whh0   = (const float*)d_in[4];
    const float* bih0   = (const float*)d_in[5];
    const float* bhh0   = (const float*)d_in[6];
    const float* Wih1   = (const float*)d_in[7];
    const float* Whh1   = (const float*)d_in[8];
    const float* bih1   = (const float*)d_in[9];
    const float* bhh1   = (const float*)d_in[10];
    const float* Wih2   = (const float*)d_in[11];
    const float* Whh2   = (const float*)d_in[12];
    const float* bih2   = (const float*)d_in[13];
    const float* bhh2   = (const float*)d_in[14];
    const float* W1     = (const float*)d_in[15];
    const float* b1     = (const float*)d_in[16];
    const float* W2     = (const float*)d_in[17];
    const float* b2     = (const float*)d_in[18];
    float* out = (float*)d_out;

    const int REC_SMEM  = 3 * BATCH * HID * 4;                    // 196608
    const int ATTN_SMEM = (BATCH * HID + SEQ * 16) * 4;           // 98304
    const int MLP_SMEM  = (16 * 2048 + 16 * 1024 + 8 * 16 * 3) * 4; // 198144
    cudaFuncSetAttribute(rec_kernel,  cudaFuncAttributeMaxDynamicSharedMemorySize, REC_SMEM);
    cudaFuncSetAttribute(attn_kernel, cudaFuncAttributeMaxDynamicSharedMemorySize, ATTN_SMEM);
    cudaFuncSetAttribute(mlp_kernel,  cudaFuncAttributeMaxDynamicSharedMemorySize, MLP_SMEM);

    p0_kernel<<<dim3(64, 4), NTHR>>>(emb, Wih0, bih0, bhh0);
    rec_kernel<<<128, NTHR, REC_SMEM>>>(tokens, Whh0, Wih1, Whh1, Wih2, Whh2,
                                        bih1, bhh1, bih2, bhh2);
    attn_kernel<<<dim3(17, 16), NTHR, ATTN_SMEM>>>(enc);
    mlp_kernel<<<TSTEPS, NTHR, MLP_SMEM>>>(tokens, W1, b1, W2, b2);
    reduce_kernel<<<1, 256>>>(out);
}

// round 6
// speedup vs baseline: 1.0508x; 1.0508x over previous
#include <cuda_runtime.h>
#include <cstdint>
#include <math.h>

#define BATCH 16
#define HID   1024
#define G4    (4*HID)
#define TSTEPS 257
#define VOC   1024
#define EMB   512
#define SEQ   512
#define ENC2D 1024
#define SOS_TOK 1
#define EOS_TOK 2
#define NTHR 256

typedef unsigned long long u64;

// ---------------- device scratch ----------------
__device__ float g_P0[VOC * G4];
__device__ float g_h[2][BATCH * HID];
__device__ float g_hs[TSTEPS * BATCH * HID];
__device__ float g_ctx[TSTEPS * BATCH * HID];
__device__ float g_partial[TSTEPS];
__device__ unsigned g_barcnt = 0;
__device__ unsigned g_bargen = 0;

__device__ __forceinline__ float4 ld4(const float* p) {
    return *reinterpret_cast<const float4*>(p);
}
__device__ __forceinline__ ulonglong2 ld2u(const float* p) {
    return *reinterpret_cast<const ulonglong2*>(p);
}
// packed fp32x2 FMA: d.lo += a.lo*b.lo ; d.hi += a.hi*b.hi
__device__ __forceinline__ void ffma2(u64& d, u64 a, u64 b) {
    asm("fma.rn.f32x2 %0, %1, %2, %0;" : "+l"(d) : "l"(a), "l"(b));
}
__device__ __forceinline__ float upksum(u64 v) {
    float x, y;
    asm("mov.b64 {%0,%1}, %2;" : "=f"(x), "=f"(y) : "l"(v));
    return x + y;
}
__device__ __forceinline__ void grid_sync() {
    __syncthreads();
    if (threadIdx.x == 0) {
        volatile unsigned* vg = &g_bargen;
        unsigned gen = *vg;
        __threadfence();
        unsigned arr = atomicAdd(&g_barcnt, 1u);
        if (arr == gridDim.x - 1) {
            g_barcnt = 0u;
            __threadfence();
            atomicAdd(&g_bargen, 1u);
        } else {
            while (*vg == gen) { __nanosleep(32); }
        }
        __threadfence();
    }
    __syncthreads();
}
__device__ __forceinline__ void wreduce16(float a[16]) {
#pragma unroll
    for (int b = 0; b < 16; b++) {
#pragma unroll
        for (int off = 16; off; off >>= 1)
            a[b] += __shfl_xor_sync(0xffffffffu, a[b], off);
    }
}
__device__ __forceinline__ float pick16(const float a[16], int lane) {
    float r = 0.f;
#pragma unroll
    for (int b = 0; b < 16; b++) r = (lane == b) ? a[b] : r;
    return r;
}
// unpack 16 packed accs, reduce across warp; lane b (b<16) gets total for b
__device__ __forceinline__ float red_gate(const u64* a, int lane) {
    float s[16];
#pragma unroll
    for (int b = 0; b < 16; b++) s[b] = upksum(a[b]);
    wreduce16(s);
    return pick16(s, lane);
}
__device__ __forceinline__ float sigmoidf_(float x) { return 1.f / (1.f + __expf(-x)); }

// Accumulate gate rows {jj, H+jj, 2H+jj, 3H+jj} of W against 16 smem vectors (packed k-pairs).
__device__ __forceinline__ void accum_gates2(const float* __restrict__ W, int jj,
                                             const float* __restrict__ sh, int lane,
                                             u64 a0[16], u64 a1[16], u64 a2[16], u64 a3[16]) {
    const float* Wi = W + (size_t)(0 * HID + jj) * HID;
    const float* Wf = W + (size_t)(1 * HID + jj) * HID;
    const float* Wg = W + (size_t)(2 * HID + jj) * HID;
    const float* Wo = W + (size_t)(3 * HID + jj) * HID;
#pragma unroll 2
    for (int i = 0; i < HID / 128; i++) {
        int k = 4 * lane + 128 * i;
        ulonglong2 wi = ld2u(Wi + k), wf = ld2u(Wf + k), wg = ld2u(Wg + k), wo = ld2u(Wo + k);
#pragma unroll
        for (int b = 0; b < 16; b++) {
            ulonglong2 h2 = ld2u(sh + b * HID + k);
            ffma2(a0[b], wi.x, h2.x); ffma2(a0[b], wi.y, h2.y);
            ffma2(a1[b], wf.x, h2.x); ffma2(a1[b], wf.y, h2.y);
            ffma2(a2[b], wg.x, h2.x); ffma2(a2[b], wg.y, h2.y);
            ffma2(a3[b], wo.x, h2.x); ffma2(a3[b], wo.y, h2.y);
        }
    }
}

// ---------------- P0: emb@W_ih0[:, :512]^T + b_ih0 + b_hh0 (j-tile 2) ----------------
__global__ void __launch_bounds__(NTHR) p0_kernel(const float* __restrict__ emb,
                                                  const float* __restrict__ Wih0,
                                                  const float* __restrict__ bih0,
                                                  const float* __restrict__ bhh0) {
    __shared__ float se[16 * EMB];
    const int tid = threadIdx.x, lane = tid & 31, w = tid >> 5;
    const int v0 = blockIdx.x * 16;
    for (int i = tid; i < 16 * EMB; i += NTHR)
        se[i] = emb[(size_t)(v0 + (i >> 9)) * EMB + (i & 511)];
    __syncthreads();
    const int jbase = blockIdx.y * 1024;
    for (int j = jbase + w * 2; j < jbase + 1024; j += 16) {
        u64 aA[16], aB[16];
#pragma unroll
        for (int b = 0; b < 16; b++) { aA[b] = 0ull; aB[b] = 0ull; }
#pragma unroll
        for (int i = 0; i < EMB / 128; i++) {
            int k = 4 * lane + 128 * i;
            ulonglong2 wA = ld2u(Wih0 + (size_t)j * (EMB + ENC2D) + k);
            ulonglong2 wB = ld2u(Wih0 + (size_t)(j + 1) * (EMB + ENC2D) + k);
#pragma unroll
            for (int v = 0; v < 16; v++) {
                ulonglong2 e2 = ld2u(se + v * EMB + k);
                ffma2(aA[v], wA.x, e2.x); ffma2(aA[v], wA.y, e2.y);
                ffma2(aB[v], wB.x, e2.x); ffma2(aB[v], wB.y, e2.y);
            }
        }
        float vA = red_gate(aA, lane), vB = red_gate(aB, lane);
        if (lane < 16) {
            g_P0[(size_t)(v0 + lane) * G4 + j]     = vA + bih0[j]     + bhh0[j];
            g_P0[(size_t)(v0 + lane) * G4 + j + 1] = vB + bih0[j + 1] + bhh0[j + 1];
        }
    }
}

// ---------------- persistent pipelined 3-layer LSTM (1 grid sync / tick) ----------------
__global__ void __launch_bounds__(NTHR, 1) rec_kernel(
    const int* __restrict__ tokens,
    const float* __restrict__ Whh0,
    const float* __restrict__ Wih1, const float* __restrict__ Whh1,
    const float* __restrict__ Wih2, const float* __restrict__ Whh2,
    const float* __restrict__ bih1, const float* __restrict__ bhh1,
    const float* __restrict__ bih2, const float* __restrict__ bhh2) {
    extern __shared__ float sm[];
    float* H0 = sm;
    float* H1 = sm + BATCH * HID;
    float* H2 = sm + 2 * BATCH * HID;
    const int tid = threadIdx.x, lane = tid & 31, w = tid >> 5;
    const int jj = blockIdx.x * 8 + w;

    for (int i = tid; i < 3 * BATCH * HID; i += NTHR) sm[i] = 0.f;
    __syncthreads();
    float c0 = 0.f, c1 = 0.f, c2 = 0.f;

    // biases for this warp's gate rows (uniform per warp)
    const float B1i = bih1[jj] + bhh1[jj];
    const float B1f = bih1[HID + jj] + bhh1[HID + jj];
    const float B1g = bih1[2 * HID + jj] + bhh1[2 * HID + jj];
    const float B1o = bih1[3 * HID + jj] + bhh1[3 * HID + jj];
    const float B2i = bih2[jj] + bhh2[jj];
    const float B2f = bih2[HID + jj] + bhh2[HID + jj];
    const float B2g = bih2[2 * HID + jj] + bhh2[2 * HID + jj];
    const float B2o = bih2[3 * HID + jj] + bhh2[3 * HID + jj];

    for (int tick = 0; tick < TSTEPS + 2; tick++) {
        // ---- layer 0 at t = tick ----
        if (tick <= TSTEPS - 1) {
            u64 a0[16], a1[16], a2[16], a3[16];
#pragma unroll
            for (int b = 0; b < 16; b++) { a0[b] = a1[b] = a2[b] = a3[b] = 0ull; }
            accum_gates2(Whh0, jj, H0, lane, a0, a1, a2, a3);
            float gi = red_gate(a0, lane), gf = red_gate(a1, lane);
            float gg = red_gate(a2, lane), go = red_gate(a3, lane);
            if (lane < BATCH) {
                int tok = (tick == 0) ? SOS_TOK : tokens[lane * 256 + (tick - 1)];
                const float* p = g_P0 + (size_t)tok * G4 + jj;
                float iv = sigmoidf_(gi + p[0]);
                float fv = sigmoidf_(gf + p[HID]);
                float gv = tanhf(gg + p[2 * HID]);
                float ov = sigmoidf_(go + p[3 * HID]);
                c0 = fv * c0 + iv * gv;
                g_h[0][lane * HID + jj] = ov * tanhf(c0);
            }
        }
        // ---- layer 1 at t = tick-1 ----
        if (tick >= 1 && tick <= TSTEPS) {
            u64 a0[16], a1[16], a2[16], a3[16];
#pragma unroll
            for (int b = 0; b < 16; b++) { a0[b] = a1[b] = a2[b] = a3[b] = 0ull; }
            accum_gates2(Wih1, jj, H0, lane, a0, a1, a2, a3);
            accum_gates2(Whh1, jj, H1, lane, a0, a1, a2, a3);
            float gi = red_gate(a0, lane), gf = red_gate(a1, lane);
            float gg = red_gate(a2, lane), go = red_gate(a3, lane);
            if (lane < BATCH) {
                float iv = sigmoidf_(gi + B1i), fv = sigmoidf_(gf + B1f);
                float gv = tanhf(gg + B1g),     ov = sigmoidf_(go + B1o);
                c1 = fv * c1 + iv * gv;
                g_h[1][lane * HID + jj] = ov * tanhf(c1);
            }
        }
        // ---- layer 2 at t = tick-2 ----
        if (tick >= 2) {
            u64 a0[16], a1[16], a2[16], a3[16];
#pragma unroll
            for (int b = 0; b < 16; b++) { a0[b] = a1[b] = a2[b] = a3[b] = 0ull; }
            accum_gates2(Wih2, jj, H1, lane, a0, a1, a2, a3);
            accum_gates2(Whh2, jj, H2, lane, a0, a1, a2, a3);
            float gi = red_gate(a0, lane), gf = red_gate(a1, lane);
            float gg = red_gate(a2, lane), go = red_gate(a3, lane);
            if (lane < BATCH) {
                float iv = sigmoidf_(gi + B2i), fv = sigmoidf_(gf + B2f);
                float gv = tanhf(gg + B2g),     ov = sigmoidf_(go + B2o);
                c2 = fv * c2 + iv * gv;
                g_hs[(size_t)(tick - 2) * (BATCH * HID) + lane * HID + jj] = ov * tanhf(c2);
            }
        }
        grid_sync();
        if (tick <= TSTEPS - 1)
            for (int i = tid; i < BATCH * HID; i += NTHR) H0[i] = __ldcg(&g_h[0][i]);
        if (tick >= 1 && tick <= TSTEPS)
            for (int i = tid; i < BATCH * HID; i += NTHR) H1[i] = __ldcg(&g_h[1][i]);
        if (tick >= 2) {
            const float* src = g_hs + (size_t)(tick - 2) * (BATCH * HID);
            for (int i = tid; i < BATCH * HID; i += NTHR) H2[i] = __ldcg(&src[i]);
        }
        __syncthreads();
    }
}

// ---------------- attention: 16 t-steps per block, one batch (s-tile 2) ----------------
__global__ void __launch_bounds__(NTHR, 1) attn_kernel(const float* __restrict__ enc) {
    extern __shared__ float sm[];
    float* sh_hs = sm;                 // [16][1024]
    float* sh_sc = sm + BATCH * HID;   // [512][16]
    const int tid = threadIdx.x, lane = tid & 31, w = tid >> 5;
    const int b = blockIdx.y, t0 = blockIdx.x * 16;

    for (int i = tid; i < 16 * HID; i += NTHR) {
        int t = t0 + (i >> 10);
        sh_hs[i] = (t < TSTEPS) ? g_hs[(size_t)t * (BATCH * HID) + b * HID + (i & 1023)] : 0.f;
    }
    __syncthreads();
    const float* encb = enc + (size_t)b * SEQ * ENC2D;

    for (int s0 = w * 2; s0 < SEQ; s0 += 16) {
        u64 aA[16], aB[16];
#pragma unroll
        for (int i = 0; i < 16; i++) { aA[i] = 0ull; aB[i] = 0ull; }
        const float* e0 = encb + (size_t)s0 * ENC2D;
        const float* e1 = e0 + ENC2D;
#pragma unroll 2
        for (int i = 0; i < ENC2D / 128; i++) {
            int k = 4 * lane + 128 * i;
            ulonglong2 ea = ld2u(e0 + k), eb = ld2u(e1 + k);
#pragma unroll
            for (int tt = 0; tt < 16; tt++) {
                ulonglong2 h2 = ld2u(sh_hs + tt * HID + k);
                ffma2(aA[tt], ea.x, h2.x); ffma2(aA[tt], ea.y, h2.y);
                ffma2(aB[tt], eb.x, h2.x); ffma2(aB[tt], eb.y, h2.y);
            }
        }
        float vA = red_gate(aA, lane), vB = red_gate(aB, lane);
        if (lane < 16) {
            sh_sc[s0 * 16 + lane] = vA;
            sh_sc[(s0 + 1) * 16 + lane] = vB;
        }
    }
    __syncthreads();

    // softmax over s for each tt; warp w handles tt = 2w, 2w+1
#pragma unroll
    for (int r = 0; r < 2; r++) {
        int tt = 2 * w + r;
        float v[16], mx = -1e30f;
#pragma unroll
        for (int i = 0; i < 16; i++) { v[i] = sh_sc[(lane + 32 * i) * 16 + tt]; mx = fmaxf(mx, v[i]); }
#pragma unroll
        for (int o = 16; o; o >>= 1) mx = fmaxf(mx, __shfl_xor_sync(0xffffffffu, mx, o));
        float sum = 0.f;
#pragma unroll
        for (int i = 0; i < 16; i++) { v[i] = __expf(v[i] - mx); sum += v[i]; }
#pragma unroll
        for (int o = 16; o; o >>= 1) sum += __shfl_xor_sync(0xffffffffu, sum, o);
        float inv = 1.f / sum;
#pragma unroll
        for (int i = 0; i < 16; i++) sh_sc[(lane + 32 * i) * 16 + tt] = v[i] * inv;
    }
    __syncthreads();

    // ctx[tt][k] = sum_s attn[tt][s] * enc[b][s][k]
    float acc[4][16];
#pragma unroll
    for (int q = 0; q < 4; q++)
#pragma unroll
        for (int tt = 0; tt < 16; tt++) acc[q][tt] = 0.f;
    for (int s = 0; s < SEQ; s++) {
        float4 a0 = ld4(sh_sc + s * 16);
        float4 a1 = ld4(sh_sc + s * 16 + 4);
        float4 a2 = ld4(sh_sc + s * 16 + 8);
        float4 a3 = ld4(sh_sc + s * 16 + 12);
        float at[16] = {a0.x,a0.y,a0.z,a0.w,a1.x,a1.y,a1.z,a1.w,
                        a2.x,a2.y,a2.z,a2.w,a3.x,a3.y,a3.z,a3.w};
#pragma unroll
        for (int q = 0; q < 4; q++) {
            float e = encb[(size_t)s * ENC2D + tid + 256 * q];
#pragma unroll
            for (int tt = 0; tt < 16; tt++) acc[q][tt] += at[tt] * e;
        }
    }
#pragma unroll
    for (int tt = 0; tt < 16; tt++) {
        int t = t0 + tt;
        if (t < TSTEPS) {
#pragma unroll
            for (int q = 0; q < 4; q++)
                g_ctx[(size_t)t * (BATCH * HID) + b * HID + tid + 256 * q] = acc[q][tt];
        }
    }
}

// ---------------- fused MLP + logits + NLL per t (j-tile 4, FFMA2) ----------------
__global__ void __launch_bounds__(NTHR, 1) mlp_kernel(
    const int* __restrict__ tokens,
    const float* __restrict__ W1, const float* __restrict__ b1,
    const float* __restrict__ W2, const float* __restrict__ b2) {
    extern __shared__ float sm[];
    float* sx = sm;                            // [16][2048]
    float* sh = sm + 16 * 2048;                // [16][1024]
    float* red = sm + 16 * 2048 + 16 * 1024;   // [8][16][3]
    const int tid = threadIdx.x, lane = tid & 31, w = tid >> 5;
    const int t = blockIdx.x;

    for (int i = tid; i < 16 * 1024; i += NTHR) {
        int b = i >> 10, k = i & 1023;
        sx[b * 2048 + k] = g_hs[(size_t)t * (BATCH * HID) + i];
        sx[b * 2048 + 1024 + k] = g_ctx[(size_t)t * (BATCH * HID) + i];
    }
    __syncthreads();

    // hidden = tanh(x @ W1^T + b1): 4 rows per warp-iteration
    for (int j0 = w * 4; j0 < 1024; j0 += 32) {
        u64 a0[16], a1[16], a2[16], a3[16];
#pragma unroll
        for (int b = 0; b < 16; b++) { a0[b] = a1[b] = a2[b] = a3[b] = 0ull; }
        const float* R0 = W1 + (size_t)j0 * 2048;
        const float* R1 = R0 + 2048;
        const float* R2 = R1 + 2048;
        const float* R3 = R2 + 2048;
#pragma unroll 2
        for (int i = 0; i < 2048 / 128; i++) {
            int k = 4 * lane + 128 * i;
            ulonglong2 w0 = ld2u(R0 + k), w1 = ld2u(R1 + k), w2 = ld2u(R2 + k), w3 = ld2u(R3 + k);
#pragma unroll
            for (int b = 0; b < 16; b++) {
                ulonglong2 x2 = ld2u(sx + b * 2048 + k);
                ffma2(a0[b], w0.x, x2.x); ffma2(a0[b], w0.y, x2.y);
                ffma2(a1[b], w1.x, x2.x); ffma2(a1[b], w1.y, x2.y);
                ffma2(a2[b], w2.x, x2.x); ffma2(a2[b], w2.y, x2.y);
                ffma2(a3[b], w3.x, x2.x); ffma2(a3[b], w3.y, x2.y);
            }
        }
        float v0 = red_gate(a0, lane), v1 = red_gate(a1, lane);
        float v2 = red_gate(a2, lane), v3 = red_gate(a3, lane);
        if (lane < 16) {
            sh[lane * 1024 + j0 + 0] = tanhf(v0 + b1[j0 + 0]);
            sh[lane * 1024 + j0 + 1] = tanhf(v1 + b1[j0 + 1]);
            sh[lane * 1024 + j0 + 2] = tanhf(v2 + b1[j0 + 2]);
            sh[lane * 1024 + j0 + 3] = tanhf(v3 + b1[j0 + 3]);
        }
    }
    __syncthreads();

    // logits + streaming logsumexp + target pick; lane b owns batch b
    float M = -1e30f, S = 0.f, TV = 0.f;
    int tgt = 0;
    if (lane < 16) tgt = (t < 256) ? tokens[lane * 256 + t] : EOS_TOK;

    for (int j0 = w * 4; j0 < 1024; j0 += 32) {
        u64 a0[16], a1[16], a2[16], a3[16];
#pragma unroll
        for (int b = 0; b < 16; b++) { a0[b] = a1[b] = a2[b] = a3[b] = 0ull; }
        const float* R0 = W2 + (size_t)j0 * 1024;
        const float* R1 = R0 + 1024;
        const float* R2 = R1 + 1024;
        const float* R3 = R2 + 1024;
#pragma unroll 2
        for (int i = 0; i < 1024 / 128; i++) {
            int k = 4 * lane + 128 * i;
            ulonglong2 w0 = ld2u(R0 + k), w1 = ld2u(R1 + k), w2 = ld2u(R2 + k), w3 = ld2u(R3 + k);
#pragma unroll
            for (int b = 0; b < 16; b++) {
                ulonglong2 h2 = ld2u(sh + b * 1024 + k);
                ffma2(a0[b], w0.x, h2.x); ffma2(a0[b], w0.y, h2.y);
                ffma2(a1[b], w1.x, h2.x); ffma2(a1[b], w1.y, h2.y);
                ffma2(a2[b], w2.x, h2.x); ffma2(a2[b], w2.y, h2.y);
                ffma2(a3[b], w3.x, h2.x); ffma2(a3[b], w3.y, h2.y);
            }
        }
        float v[4];
        v[0] = red_gate(a0, lane); v[1] = red_gate(a1, lane);
        v[2] = red_gate(a2, lane); v[3] = red_gate(a3, lane);
        if (lane < 16) {
#pragma unroll
            for (int r = 0; r < 4; r++) {
                float val = v[r] + b2[j0 + r];
                float mn = fmaxf(M, val);
                S = S * __expf(M - mn) + __expf(val - mn);
                M = mn;
                if (j0 + r == tgt) TV = val;
            }
        }
    }
    if (lane < 16) {
        red[(w * 16 + lane) * 3 + 0] = M;
        red[(w * 16 + lane) * 3 + 1] = S;
        red[(w * 16 + lane) * 3 + 2] = TV;
    }
    __syncthreads();
    if (w == 0 && lane < 16) {
        float m = -1e30f, s = 0.f, tv = 0.f;
        for (int ww = 0; ww < 8; ww++) {
            float mw = red[(ww * 16 + lane) * 3 + 0];
            float sw = red[(ww * 16 + lane) * 3 + 1];
            tv += red[(ww * 16 + lane) * 3 + 2];
            float mn = fmaxf(m, mw);
            s = s * __expf(m - mn) + sw * __expf(mw - mn);
            m = mn;
        }
        float nll = (m + logf(s)) - tv;
#pragma unroll
        for (int o = 8; o; o >>= 1) nll += __shfl_xor_sync(0xffffu, nll, o);
        if (lane == 0) g_partial[t] = nll;
    }
}

__global__ void reduce_kernel(float* out) {
    __shared__ float s[256];
    int tid = threadIdx.x;
    float v = g_partial[tid];
    if (tid == 0) v += g_partial[256];
    s[tid] = v; __syncthreads();
    for (int o = 128; o; o >>= 1) { if (tid < o) s[tid] += s[tid + o]; __syncthreads(); }
    if (tid == 0) out[0] = s[0] / (float)(TSTEPS * BATCH);
}

extern "C" void kernel_launch(void* const* d_in, const int* in_sizes, int n_in,
                              void* d_out, int out_size) {
    const int*   tokens = (const int*)d_in[0];
    const float* enc    = (const float*)d_in[1];
    const float* emb    = (const float*)d_in[2];
    const float* Wih0   = (const float*)d_in[3];
    const float* Whh0   = (const float*)d_in[4];
    const float* bih0   = (const float*)d_in[5];
    const float* bhh0   = (const float*)d_in[6];
    const float* Wih1   = (const float*)d_in[7];
    const float* Whh1   = (const float*)d_in[8];
    const float* bih1   = (const float*)d_in[9];
    const float* bhh1   = (const float*)d_in[10];
    const float* Wih2   = (const float*)d_in[11];
    const float* Whh2   = (const float*)d_in[12];
    const float* bih2   = (const float*)d_in[13];
    const float* bhh2   = (const float*)d_in[14];
    const float* W1     = (const float*)d_in[15];
    const float* b1     = (const float*)d_in[16];
    const float* W2     = (const float*)d_in[17];
    const float* b2     = (const float*)d_in[18];
    float* out = (float*)d_out;

    const int REC_SMEM  = 3 * BATCH * HID * 4;                      // 196608
    const int ATTN_SMEM = (BATCH * HID + SEQ * 16) * 4;             // 98304
    const int MLP_SMEM  = (16 * 2048 + 16 * 1024 + 8 * 16 * 3) * 4; // 198144
    cudaFuncSetAttribute(rec_kernel,  cudaFuncAttributeMaxDynamicSharedMemorySize, REC_SMEM);
    cudaFuncSetAttribute(attn_kernel, cudaFuncAttributeMaxDynamicSharedMemorySize, ATTN_SMEM);
    cudaFuncSetAttribute(mlp_kernel,  cudaFuncAttributeMaxDynamicSharedMemorySize, MLP_SMEM);

    p0_kernel<<<dim3(64, 4), NTHR>>>(emb, Wih0, bih0, bhh0);
    rec_kernel<<<128, NTHR, REC_SMEM>>>(tokens, Whh0, Wih1, Whh1, Wih2, Whh2,
                                        bih1, bhh1, bih2, bhh2);
    attn_kernel<<<dim3(17, 16), NTHR, ATTN_SMEM>>>(enc);
    mlp_kernel<<<TSTEPS, NTHR, MLP_SMEM>>>(tokens, W1, b1, W2, b2);
    reduce_kernel<<<1, 256>>>(out);
}

// round 7
// speedup vs baseline: 2.8915x; 2.7518x over previous
#include <cuda_runtime.h>
#include <cuda_bf16.h>
#include <cstdint>
#include <math.h>

#define BATCH 16
#define HID   1024
#define G4    (4*HID)
#define TSTEPS 257
#define VOC   1024
#define EMB   512
#define SEQ   512
#define ENC2D 1024
#define SOS_TOK 1
#define EOS_TOK 2
#define NTHR 256

typedef unsigned long long u64;
typedef unsigned int u32;

// weight-fragment buffer sizes (bf16 elems)
#define WB_B0 0u
#define WB_B1 4194304u
#define WB_B2 12582912u
#define WB_TOT 20971520u

// ---------------- device scratch ----------------
__device__ float g_P0[VOC * G4];                       // 16 MB
__device__ __align__(16) __nv_bfloat16 g_Wb[WB_TOT];   // 40 MB fragment-ordered weights
__device__ __align__(16) __nv_bfloat16 g_hb[3][BATCH * HID];
__device__ float g_hs[TSTEPS * BATCH * HID];
__device__ float g_ctx[TSTEPS * BATCH * HID];
__device__ float g_partial[TSTEPS];
__device__ unsigned g_barcnt = 0;
__device__ unsigned g_bargen = 0;

__device__ __forceinline__ float4 ld4(const float* p) {
    return *reinterpret_cast<const float4*>(p);
}
__device__ __forceinline__ ulonglong2 ld2u(const float* p) {
    return *reinterpret_cast<const ulonglong2*>(p);
}
__device__ __forceinline__ void ffma2(u64& d, u64 a, u64 b) {
    asm("fma.rn.f32x2 %0, %1, %2, %0;" : "+l"(d) : "l"(a), "l"(b));
}
__device__ __forceinline__ float upksum(u64 v) {
    float x, y;
    asm("mov.b64 {%0,%1}, %2;" : "=f"(x), "=f"(y) : "l"(v));
    return x + y;
}
__device__ __forceinline__ u32 smem_u32(const void* p) {
    u32 a;
    asm("{ .reg .u64 t; cvta.to.shared.u64 t, %1; cvt.u32.u64 %0, t; }" : "=r"(a) : "l"(p));
    return a;
}
__device__ __forceinline__ void grid_sync() {
    __syncthreads();
    if (threadIdx.x == 0) {
        volatile unsigned* vg = &g_bargen;
        unsigned gen = *vg;
        __threadfence();
        unsigned arr = atomicAdd(&g_barcnt, 1u);
        if (arr == gridDim.x - 1) {
            g_barcnt = 0u;
            __threadfence();
            atomicAdd(&g_bargen, 1u);
        } else {
            while (*vg == gen) { __nanosleep(32); }
        }
        __threadfence();
    }
    __syncthreads();
}
__device__ __forceinline__ void wreduce16(float a[16]) {
#pragma unroll
    for (int b = 0; b < 16; b++) {
#pragma unroll
        for (int off = 16; off; off >>= 1)
            a[b] += __shfl_xor_sync(0xffffffffu, a[b], off);
    }
}
__device__ __forceinline__ float pick16(const float a[16], int lane) {
    float r = 0.f;
#pragma unroll
    for (int b = 0; b < 16; b++) r = (lane == b) ? a[b] : r;
    return r;
}
__device__ __forceinline__ float red_gate(const u64* a, int lane) {
    float s[16];
#pragma unroll
    for (int b = 0; b < 16; b++) s[b] = upksum(a[b]);
    wreduce16(s);
    return pick16(s, lane);
}
__device__ __forceinline__ float sigmoidf_(float x) { return 1.f / (1.f + __expf(-x)); }
__device__ __forceinline__ float gate_h(float gi, float gf, float gG, float go, float& c) {
    float iv = sigmoidf_(gi), fv = sigmoidf_(gf);
    float gv = tanhf(gG), ov = sigmoidf_(go);
    c = fv * c + iv * gv;
    return ov * tanhf(c);
}

// ---------------- weight prepass: fp32 -> bf16 in per-thread mma B-fragment order --------
// layout: [layer][chunk(512)][half(2)][kstep][lane(32)][reg(2)][elem(2)]
// k = half*Kh + kstep*16 + (lane%4)*2 + 8*reg + elem ; n = lane/4 ; gate = n&3 ; jl = n>>2
// W row = gate*1024 + 2*chunk + jl
__global__ void __launch_bounds__(NTHR) prep_w(
    const float* __restrict__ Whh0,
    const float* __restrict__ Wih1, const float* __restrict__ Whh1,
    const float* __restrict__ Wih2, const float* __restrict__ Whh2) {
    for (u32 idx = blockIdx.x * NTHR + threadIdx.x; idx < WB_TOT; idx += gridDim.x * NTHR) {
        int l, Kh, steps; u32 base;
        if (idx < WB_B1)      { l = 0; Kh = 512;  steps = 32; base = WB_B0; }
        else if (idx < WB_B2) { l = 1; Kh = 1024; steps = 64; base = WB_B1; }
        else                  { l = 2; Kh = 1024; steps = 64; base = WB_B2; }
        u32 within = idx - base;
        int pc = 2 * steps * 128;
        int c = within / pc;   int r1 = within % pc;
        int h = r1 / (steps * 128); int r2 = r1 % (steps * 128);
        int s = r2 / 128;      int q  = r2 % 128;
        int lane = q >> 2;     int rr = (q >> 1) & 1; int e = q & 1;
        int k = h * Kh + s * 16 + (lane & 3) * 2 + 8 * rr + e;
        int n = lane >> 2;     int gate = n & 3;      int jl = n >> 2;
        int row = gate * 1024 + 2 * c + jl;
        float v;
        if (l == 0)      v = Whh0[(size_t)row * 1024 + k];
        else if (l == 1) v = (k < 1024) ? Wih1[(size_t)row * 1024 + k]
                                        : Whh1[(size_t)row * 1024 + k - 1024];
        else             v = (k < 1024) ? Wih2[(size_t)row * 1024 + k]
                                        : Whh2[(size_t)row * 1024 + k - 1024];
        g_Wb[idx] = __float2bfloat16(v);
    }
}

// ---------------- P0: emb@W_ih0[:, :512]^T + b_ih0 + b_hh0 ----------------
__global__ void __launch_bounds__(NTHR) p0_kernel(const float* __restrict__ emb,
                                                  const float* __restrict__ Wih0,
                                                  const float* __restrict__ bih0,
                                                  const float* __restrict__ bhh0) {
    __shared__ float se[16 * EMB];
    const int tid = threadIdx.x, lane = tid & 31, w = tid >> 5;
    const int v0 = blockIdx.x * 16;
    for (int i = tid; i < 16 * EMB; i += NTHR)
        se[i] = emb[(size_t)(v0 + (i >> 9)) * EMB + (i & 511)];
    __syncthreads();
    const int jbase = blockIdx.y * 1024;
    for (int j = jbase + w * 2; j < jbase + 1024; j += 16) {
        u64 aA[16], aB[16];
#pragma unroll
        for (int b = 0; b < 16; b++) { aA[b] = 0ull; aB[b] = 0ull; }
#pragma unroll
        for (int i = 0; i < EMB / 128; i++) {
            int k = 4 * lane + 128 * i;
            ulonglong2 wA = ld2u(Wih0 + (size_t)j * (EMB + ENC2D) + k);
            ulonglong2 wB = ld2u(Wih0 + (size_t)(j + 1) * (EMB + ENC2D) + k);
#pragma unroll
            for (int v = 0; v < 16; v++) {
                ulonglong2 e2 = ld2u(se + v * EMB + k);
                ffma2(aA[v], wA.x, e2.x); ffma2(aA[v], wA.y, e2.y);
                ffma2(aB[v], wB.x, e2.x); ffma2(aB[v], wB.y, e2.y);
            }
        }
        float vA = red_gate(aA, lane), vB = red_gate(aB, lane);
        if (lane < 16) {
            g_P0[(size_t)(v0 + lane) * G4 + j]     = vA + bih0[j]     + bhh0[j];
            g_P0[(size_t)(v0 + lane) * G4 + j + 1] = vB + bih0[j + 1] + bhh0[j + 1];
        }
    }
}

// ---------------- tensor-core recurrence ----------------
// smem: X0/X1/X2: 16 rows x 1032 bf16 (stride 2064 B) at 0 / 33024 / 66048
//       pair scratch: 4 pairs x 1024 B at 99072 ; total 103168 B
#define XSTRIDE 2064
#define XSZ     33024
#define PAIROFF 99072
#define REC_SMEM 103168

template<int STEPS>
__device__ __forceinline__ void mma_loop(u32 addr, const __nv_bfloat16* wp, int lane,
                                         float& d0, float& d1, float& d2, float& d3) {
    d0 = d1 = d2 = d3 = 0.f;
    const u64* wq = reinterpret_cast<const u64*>(wp + lane * 4);
#pragma unroll 8
    for (int s = 0; s < STEPS; s++) {
        u32 a0, a1, a2, a3;
        asm volatile("ldmatrix.sync.aligned.m8n8.x4.shared.b16 {%0,%1,%2,%3}, [%4];"
            : "=r"(a0), "=r"(a1), "=r"(a2), "=r"(a3) : "r"(addr));
        u64 bw = wq[s * 32];
        u32 b0 = (u32)bw, b1 = (u32)(bw >> 32);
        asm volatile("mma.sync.aligned.m16n8k16.row.col.f32.bf16.bf16.f32 "
            "{%0,%1,%2,%3}, {%4,%5,%6,%7}, {%8,%9}, {%0,%1,%2,%3};"
            : "+f"(d0), "+f"(d1), "+f"(d2), "+f"(d3)
            : "r"(a0), "r"(a1), "r"(a2), "r"(a3), "r"(b0), "r"(b1));
        addr += 32;
    }
}

// odd warp ships partial D; even warp sums and lays gates out as [jl][gate][b]
__device__ __forceinline__ void combine(float* pp, float* gg, int half, int lane, int barid,
                                        float d0, float d1, float d2, float d3) {
    if (half) {
        ((float4*)pp)[lane] = make_float4(d0, d1, d2, d3);
        asm volatile("bar.sync %0, 64;" :: "r"(barid) : "memory");
    } else {
        asm volatile("bar.sync %0, 64;" :: "r"(barid) : "memory");
        float4 q = ((float4*)pp)[lane];
        d0 += q.x; d1 += q.y; d2 += q.z; d3 += q.w;
        int r = lane >> 2, cc = (lane & 3) * 2;
        gg[((cc    ) >> 2) * 64 + ((cc    ) & 3) * 16 + r    ] = d0;
        gg[((cc + 1) >> 2) * 64 + ((cc + 1) & 3) * 16 + r    ] = d1;
        gg[((cc    ) >> 2) * 64 + ((cc    ) & 3) * 16 + r + 8] = d2;
        gg[((cc + 1) >> 2) * 64 + ((cc + 1) & 3) * 16 + r + 8] = d3;
        __syncwarp();
    }
}

__global__ void __launch_bounds__(NTHR, 1) rec_kernel(
    const int* __restrict__ tokens,
    const float* __restrict__ bih1, const float* __restrict__ bhh1,
    const float* __restrict__ bih2, const float* __restrict__ bhh2) {
    extern __shared__ char smem[];
    const int tid = threadIdx.x, lane = tid & 31, w = tid >> 5;
    const int pairid = w >> 1, half = w & 1;
    const int chunk = blockIdx.x * 4 + pairid;
    const int j0 = chunk * 2;
    const int bL = lane & 15, jl = lane >> 4, jg = j0 + jl;
    const int barid = pairid + 1;

    u32 sb = smem_u32(smem);
    const int arow = lane & 15;
    const int acolb = ((lane >= 16) ? 8 : 0) * 2;   // byte offset of k+8 tiles
    u32 xa0 = sb + arow * XSTRIDE + acolb;
    u32 xa1 = xa0 + XSZ;
    u32 xa2 = xa1 + XSZ;
    float* pp = (float*)(smem + PAIROFF + pairid * 1024);
    float* gg = pp + 128;

    for (int i = tid; i < (3 * XSZ) / 4; i += NTHR) ((u32*)smem)[i] = 0u;
    __syncthreads();

    const __nv_bfloat16* w0 = g_Wb + WB_B0 + (size_t)(chunk * 2 + half) * 32 * 128;
    const __nv_bfloat16* w1 = g_Wb + WB_B1 + (size_t)(chunk * 2 + half) * 64 * 128;
    const __nv_bfloat16* w2 = g_Wb + WB_B2 + (size_t)(chunk * 2 + half) * 64 * 128;

    float B1g[4], B2g[4];
#pragma unroll
    for (int gt = 0; gt < 4; gt++) {
        B1g[gt] = bih1[gt * 1024 + jg] + bhh1[gt * 1024 + jg];
        B2g[gt] = bih2[gt * 1024 + jg] + bhh2[gt * 1024 + jg];
    }
    float c0 = 0.f, c1 = 0.f, c2 = 0.f;

    for (int tick = 0; tick < TSTEPS + 2; tick++) {
        // ---- layer 0 at t = tick ----
        if (tick <= 256) {
            float d0, d1, d2, d3;
            mma_loop<32>(xa0 + (half ? 1024 : 0), w0, lane, d0, d1, d2, d3);
            combine(pp, gg, half, lane, barid, d0, d1, d2, d3);
            if (!half) {
                int tok = (tick == 0) ? SOS_TOK : tokens[bL * 256 + tick - 1];
                const float* p = g_P0 + (size_t)tok * G4 + jg;
                float h = gate_h(gg[jl * 64 + bL] + p[0],
                                 gg[jl * 64 + 16 + bL] + p[1024],
                                 gg[jl * 64 + 32 + bL] + p[2048],
                                 gg[jl * 64 + 48 + bL] + p[3072], c0);
                g_hb[0][bL * 1024 + jg] = __float2bfloat16(h);
            }
            asm volatile("bar.sync %0, 64;" :: "r"(barid) : "memory");
        }
        // ---- layer 1 at t = tick-1 ----
        if (tick >= 1 && tick <= 257) {
            float d0, d1, d2, d3;
            mma_loop<64>(half ? xa1 : xa0, w1, lane, d0, d1, d2, d3);
            combine(pp, gg, half, lane, barid, d0, d1, d2, d3);
            if (!half) {
                float h = gate_h(gg[jl * 64 + bL] + B1g[0],
                                 gg[jl * 64 + 16 + bL] + B1g[1],
                                 gg[jl * 64 + 32 + bL] + B1g[2],
                                 gg[jl * 64 + 48 + bL] + B1g[3], c1);
                g_hb[1][bL * 1024 + jg] = __float2bfloat16(h);
            }
            asm volatile("bar.sync %0, 64;" :: "r"(barid) : "memory");
        }
        // ---- layer 2 at t = tick-2 ----
        if (tick >= 2) {
            float d0, d1, d2, d3;
            mma_loop<64>(half ? xa2 : xa1, w2, lane, d0, d1, d2, d3);
            combine(pp, gg, half, lane, barid, d0, d1, d2, d3);
            if (!half) {
                float h = gate_h(gg[jl * 64 + bL] + B2g[0],
                                 gg[jl * 64 + 16 + bL] + B2g[1],
                                 gg[jl * 64 + 32 + bL] + B2g[2],
                                 gg[jl * 64 + 48 + bL] + B2g[3], c2);
                g_hb[2][bL * 1024 + jg] = __float2bfloat16(h);
                g_hs[(size_t)(tick - 2) * (BATCH * HID) + bL * 1024 + jg] = h;
            }
            asm volatile("bar.sync %0, 64;" :: "r"(barid) : "memory");
        }
        grid_sync();
        // reload h states into padded smem (bf16, u64 chunks: 2048 per array)
        if (tick <= 256)
            for (int i = tid; i < 2048; i += NTHR) {
                u64 v = __ldcg((const u64*)(g_hb[0]) + i);
                *(u64*)(smem + (i >> 8) * XSTRIDE + (i & 255) * 8) = v;
            }
        if (tick >= 1 && tick <= 257)
            for (int i = tid; i < 2048; i += NTHR) {
                u64 v = __ldcg((const u64*)(g_hb[1]) + i);
                *(u64*)(smem + XSZ + (i >> 8) * XSTRIDE + (i & 255) * 8) = v;
            }
        if (tick >= 2 && tick <= 257)
            for (int i = tid; i < 2048; i += NTHR) {
                u64 v = __ldcg((const u64*)(g_hb[2]) + i);
                *(u64*)(smem + 2 * XSZ + (i >> 8) * XSTRIDE + (i & 255) * 8) = v;
            }
        __syncthreads();
    }
}

// ---------------- attention: 16 t-steps per block, one batch ----------------
__global__ void __launch_bounds__(NTHR, 1) attn_kernel(const float* __restrict__ enc) {
    extern __shared__ float sm[];
    float* sh_hs = sm;                 // [16][1024]
    float* sh_sc = sm + BATCH * HID;   // [512][16]
    const int tid = threadIdx.x, lane = tid & 31, w = tid >> 5;
    const int b = blockIdx.y, t0 = blockIdx.x * 16;

    for (int i = tid; i < 16 * HID; i += NTHR) {
        int t = t0 + (i >> 10);
        sh_hs[i] = (t < TSTEPS) ? g_hs[(size_t)t * (BATCH * HID) + b * HID + (i & 1023)] : 0.f;
    }
    __syncthreads();
    const float* encb = enc + (size_t)b * SEQ * ENC2D;

    for (int s0 = w * 2; s0 < SEQ; s0 += 16) {
        u64 aA[16], aB[16];
#pragma unroll
        for (int i = 0; i < 16; i++) { aA[i] = 0ull; aB[i] = 0ull; }
        const float* e0 = encb + (size_t)s0 * ENC2D;
        const float* e1 = e0 + ENC2D;
#pragma unroll 2
        for (int i = 0; i < ENC2D / 128; i++) {
            int k = 4 * lane + 128 * i;
            ulonglong2 ea = ld2u(e0 + k), eb = ld2u(e1 + k);
#pragma unroll
            for (int tt = 0; tt < 16; tt++) {
                ulonglong2 h2 = ld2u(sh_hs + tt * HID + k);
                ffma2(aA[tt], ea.x, h2.x); ffma2(aA[tt], ea.y, h2.y);
                ffma2(aB[tt], eb.x, h2.x); ffma2(aB[tt], eb.y, h2.y);
            }
        }
        float vA = red_gate(aA, lane), vB = red_gate(aB, lane);
        if (lane < 16) {
            sh_sc[s0 * 16 + lane] = vA;
            sh_sc[(s0 + 1) * 16 + lane] = vB;
        }
    }
    __syncthreads();

#pragma unroll
    for (int r = 0; r < 2; r++) {
        int tt = 2 * w + r;
        float v[16], mx = -1e30f;
#pragma unroll
        for (int i = 0; i < 16; i++) { v[i] = sh_sc[(lane + 32 * i) * 16 + tt]; mx = fmaxf(mx, v[i]); }
#pragma unroll
        for (int o = 16; o; o >>= 1) mx = fmaxf(mx, __shfl_xor_sync(0xffffffffu, mx, o));
        float sum = 0.f;
#pragma unroll
        for (int i = 0; i < 16; i++) { v[i] = __expf(v[i] - mx); sum += v[i]; }
#pragma unroll
        for (int o = 16; o; o >>= 1) sum += __shfl_xor_sync(0xffffffffu, sum, o);
        float inv = 1.f / sum;
#pragma unroll
        for (int i = 0; i < 16; i++) sh_sc[(lane + 32 * i) * 16 + tt] = v[i] * inv;
    }
    __syncthreads();

    float acc[4][16];
#pragma unroll
    for (int q = 0; q < 4; q++)
#pragma unroll
        for (int tt = 0; tt < 16; tt++) acc[q][tt] = 0.f;
    for (int s = 0; s < SEQ; s++) {
        float4 a0 = ld4(sh_sc + s * 16);
        float4 a1 = ld4(sh_sc + s * 16 + 4);
        float4 a2 = ld4(sh_sc + s * 16 + 8);
        float4 a3 = ld4(sh_sc + s * 16 + 12);
        float at[16] = {a0.x,a0.y,a0.z,a0.w,a1.x,a1.y,a1.z,a1.w,
                        a2.x,a2.y,a2.z,a2.w,a3.x,a3.y,a3.z,a3.w};
#pragma unroll
        for (int q = 0; q < 4; q++) {
            float e = encb[(size_t)s * ENC2D + tid + 256 * q];
#pragma unroll
            for (int tt = 0; tt < 16; tt++) acc[q][tt] += at[tt] * e;
        }
    }
#pragma unroll
    for (int tt = 0; tt < 16; tt++) {
        int t = t0 + tt;
        if (t < TSTEPS) {
#pragma unroll
            for (int q = 0; q < 4; q++)
                g_ctx[(size_t)t * (BATCH * HID) + b * HID + tid + 256 * q] = acc[q][tt];
        }
    }
}

// ---------------- fused MLP + logits + NLL per t ----------------
__global__ void __launch_bounds__(NTHR, 1) mlp_kernel(
    const int* __restrict__ tokens,
    const float* __restrict__ W1, const float* __restrict__ b1,
    const float* __restrict__ W2, const float* __restrict__ b2) {
    extern __shared__ float sm[];
    float* sx = sm;                            // [16][2048]
    float* sh = sm + 16 * 2048;                // [16][1024]
    float* red = sm + 16 * 2048 + 16 * 1024;   // [8][16][3]
    const int tid = threadIdx.x, lane = tid & 31, w = tid >> 5;
    const int t = blockIdx.x;

    for (int i = tid; i < 16 * 1024; i += NTHR) {
        int b = i >> 10, k = i & 1023;
        sx[b * 2048 + k] = g_hs[(size_t)t * (BATCH * HID) + i];
        sx[b * 2048 + 1024 + k] = g_ctx[(size_t)t * (BATCH * HID) + i];
    }
    __syncthreads();

    for (int j0 = w * 4; j0 < 1024; j0 += 32) {
        u64 a0[16], a1[16], a2[16], a3[16];
#pragma unroll
        for (int b = 0; b < 16; b++) { a0[b] = a1[b] = a2[b] = a3[b] = 0ull; }
        const float* R0 = W1 + (size_t)j0 * 2048;
        const float* R1 = R0 + 2048;
        const float* R2 = R1 + 2048;
        const float* R3 = R2 + 2048;
#pragma unroll 2
        for (int i = 0; i < 2048 / 128; i++) {
            int k = 4 * lane + 128 * i;
            ulonglong2 w0 = ld2u(R0 + k), w1 = ld2u(R1 + k), w2 = ld2u(R2 + k), w3 = ld2u(R3 + k);
#pragma unroll
            for (int b = 0; b < 16; b++) {
                ulonglong2 x2 = ld2u(sx + b * 2048 + k);
                ffma2(a0[b], w0.x, x2.x); ffma2(a0[b], w0.y, x2.y);
                ffma2(a1[b], w1.x, x2.x); ffma2(a1[b], w1.y, x2.y);
                ffma2(a2[b], w2.x, x2.x); ffma2(a2[b], w2.y, x2.y);
                ffma2(a3[b], w3.x, x2.x); ffma2(a3[b], w3.y, x2.y);
            }
        }
        float v0 = red_gate(a0, lane), v1 = red_gate(a1, lane);
        float v2 = red_gate(a2, lane), v3 = red_gate(a3, lane);
        if (lane < 16) {
            sh[lane * 1024 + j0 + 0] = tanhf(v0 + b1[j0 + 0]);
            sh[lane * 1024 + j0 + 1] = tanhf(v1 + b1[j0 + 1]);
            sh[lane * 1024 + j0 + 2] = tanhf(v2 + b1[j0 + 2]);
            sh[lane * 1024 + j0 + 3] = tanhf(v3 + b1[j0 + 3]);
        }
    }
    __syncthreads();

    float M = -1e30f, S = 0.f, TV = 0.f;
    int tgt = 0;
    if (lane < 16) tgt = (t < 256) ? tokens[lane * 256 + t] : EOS_TOK;

    for (int j0 = w * 4; j0 < 1024; j0 += 32) {
        u64 a0[16], a1[16], a2[16], a3[16];
#pragma unroll
        for (int b = 0; b < 16; b++) { a0[b] = a1[b] = a2[b] = a3[b] = 0ull; }
        const float* R0 = W2 + (size_t)j0 * 1024;
        const float* R1 = R0 + 1024;
        const float* R2 = R1 + 1024;
        const float* R3 = R2 + 1024;
#pragma unroll 2
        for (int i = 0; i < 1024 / 128; i++) {
            int k = 4 * lane + 128 * i;
            ulonglong2 w0 = ld2u(R0 + k), w1 = ld2u(R1 + k), w2 = ld2u(R2 + k), w3 = ld2u(R3 + k);
#pragma unroll
            for (int b = 0; b < 16; b++) {
                ulonglong2 h2 = ld2u(sh + b * 1024 + k);
                ffma2(a0[b], w0.x, h2.x); ffma2(a0[b], w0.y, h2.y);
                ffma2(a1[b], w1.x, h2.x); ffma2(a1[b], w1.y, h2.y);
                ffma2(a2[b], w2.x, h2.x); ffma2(a2[b], w2.y, h2.y);
                ffma2(a3[b], w3.x, h2.x); ffma2(a3[b], w3.y, h2.y);
            }
        }
        float v[4];
        v[0] = red_gate(a0, lane); v[1] = red_gate(a1, lane);
        v[2] = red_gate(a2, lane); v[3] = red_gate(a3, lane);
        if (lane < 16) {
#pragma unroll
            for (int r = 0; r < 4; r++) {
                float val = v[r] + b2[j0 + r];
                float mn = fmaxf(M, val);
                S = S * __expf(M - mn) + __expf(val - mn);
                M = mn;
                if (j0 + r == tgt) TV = val;
            }
        }
    }
    if (lane < 16) {
        red[(w * 16 + lane) * 3 + 0] = M;
        red[(w * 16 + lane) * 3 + 1] = S;
        red[(w * 16 + lane) * 3 + 2] = TV;
    }
    __syncthreads();
    if (w == 0 && lane < 16) {
        float m = -1e30f, s = 0.f, tv = 0.f;
        for (int ww = 0; ww < 8; ww++) {
            float mw = red[(ww * 16 + lane) * 3 + 0];
            float sw = red[(ww * 16 + lane) * 3 + 1];
            tv += red[(ww * 16 + lane) * 3 + 2];
            float mn = fmaxf(m, mw);
            s = s * __expf(m - mn) + sw * __expf(mw - mn);
            m = mn;
        }
        float nll = (m + logf(s)) - tv;
#pragma unroll
        for (int o = 8; o; o >>= 1) nll += __shfl_xor_sync(0xffffu, nll, o);
        if (lane == 0) g_partial[t] = nll;
    }
}

__global__ void reduce_kernel(float* out) {
    __shared__ float s[256];
    int tid = threadIdx.x;
    float v = g_partial[tid];
    if (tid == 0) v += g_partial[256];
    s[tid] = v; __syncthreads();
    for (int o = 128; o; o >>= 1) { if (tid < o) s[tid] += s[tid + o]; __syncthreads(); }
    if (tid == 0) out[0] = s[0] / (float)(TSTEPS * BATCH);
}

extern "C" void kernel_launch(void* const* d_in, const int* in_sizes, int n_in,
                              void* d_out, int out_size) {
    const int*   tokens = (const int*)d_in[0];
    const float* enc    = (const float*)d_in[1];
    const float* emb    = (const float*)d_in[2];
    const float* Wih0   = (const float*)d_in[3];
    const float* Whh0   = (const float*)d_in[4];
    const float* bih0   = (const float*)d_in[5];
    const float* bhh0   = (const float*)d_in[6];
    const float* Wih1   = (const float*)d_in[7];
    const float* Whh1   = (const float*)d_in[8];
    const float* bih1   = (const float*)d_in[9];
    const float* bhh1   = (const float*)d_in[10];
    const float* Wih2   = (const float*)d_in[11];
    const float* Whh2   = (const float*)d_in[12];
    const float* bih2   = (const float*)d_in[13];
    const float* bhh2   = (const float*)d_in[14];
    const float* W1     = (const float*)d_in[15];
    const float* b1     = (const float*)d_in[16];
    const float* W2     = (const float*)d_in[17];
    const float* b2     = (const float*)d_in[18];
    float* out = (float*)d_out;

    const int ATTN_SMEM = (BATCH * HID + SEQ * 16) * 4;
    const int MLP_SMEM  = (16 * 2048 + 16 * 1024 + 8 * 16 * 3) * 4;
    cudaFuncSetAttribute(rec_kernel,  cudaFuncAttributeMaxDynamicSharedMemorySize, REC_SMEM);
    cudaFuncSetAttribute(attn_kernel, cudaFuncAttributeMaxDynamicSharedMemorySize, ATTN_SMEM);
    cudaFuncSetAttribute(mlp_kernel,  cudaFuncAttributeMaxDynamicSharedMemorySize, MLP_SMEM);

    prep_w<<<2048, NTHR>>>(Whh0, Wih1, Whh1, Wih2, Whh2);
    p0_kernel<<<dim3(64, 4), NTHR>>>(emb, Wih0, bih0, bhh0);
    rec_kernel<<<128, NTHR, REC_SMEM>>>(tokens, bih1, bhh1, bih2, bhh2);
    attn_kernel<<<dim3(17, 16), NTHR, ATTN_SMEM>>>(enc);
    mlp_kernel<<<TSTEPS, NTHR, MLP_SMEM>>>(tokens, W1, b1, W2, b2);
    reduce_kernel<<<1, 256>>>(out);
}